// round 6
// baseline (speedup 1.0000x reference)
#include <cuda_runtime.h>
#include <cstdint>

// DConv implicit GEMM, mma.sync tf32 (legacy TC path; tcgen05 blocked by
// compute_103 virtual arch in the harness build).
//
// Per (b, y):  D[o][x] = sum_k W[o][k] * B[k][x],  K = 576, k = c*9 + ky*3 + kx
//   B[k][x] = xz[c][y-1+ky-dy_c][x+kx-1-dx_c]   (zero outside [0,160)^2)
//   (dx,dy) from c%5: 0:(0,0) 1:(1,0) 2:(0,1) 3:(-1,0) 4:(0,-1)
//
// R5: warp grid 2M x 4N (warp tile m32 x n40) to cut B LDS re-reads;
// K chunks of 48 (12 chunks, double-buffered) -> 91KB smem -> 2 CTAs/SM.

#define HH 160
#define WW 160
#define CIN 64
#define COUT 64
#define THREADS 256
#define NCHUNK 12
#define KCH 48                         // K rows per chunk (6 k-steps of 8)

#define DESC_OFF 0                     // 576 x int2 = 4608 B
#define BUF_OFF  4608
#define A_BYTES  12288                 // 4 mfrag x 6 ks x 32 lane x 16B
#define B_BYTES  30720                 // 20 nfrag x 6 ks x 32 lane x 8B
#define BUF_STRIDE (A_BYTES + B_BYTES)         // 43008
#define SMEM_TOTAL (BUF_OFF + 2 * BUF_STRIDE)  // 90624

__device__ __forceinline__ uint32_t f2tf(float f) {
    uint32_t r;
    asm("cvt.rna.tf32.f32 %0, %1;" : "=r"(r) : "f"(f));
    return r;
}

__device__ __forceinline__ void mma_tf32(float* c, uint4 a, uint2 b) {
    asm volatile(
        "mma.sync.aligned.m16n8k8.row.col.f32.tf32.tf32.f32 "
        "{%0,%1,%2,%3}, {%4,%5,%6,%7}, {%8,%9}, {%0,%1,%2,%3};"
        : "+f"(c[0]), "+f"(c[1]), "+f"(c[2]), "+f"(c[3])
        : "r"(a.x), "r"(a.y), "r"(a.z), "r"(a.w), "r"(b.x), "r"(b.y));
}

extern __shared__ char smem[];

__global__ __launch_bounds__(THREADS, 2)
void dconv_mma_kernel(const float* __restrict__ x,
                      const float* __restrict__ w,
                      float* __restrict__ out)
{
    const int y    = blockIdx.x;
    const int b    = blockIdx.y;
    const int tid  = threadIdx.x;
    const int lane = tid & 31;
    const int wid  = tid >> 5;
    const int g  = lane >> 2;          // groupID (row / pixel within frag)
    const int t  = lane & 3;           // thread-in-group (k within frag)
    const int fm = wid & 1;            // M-warp: o block of 32
    const int wn = wid >> 1;           // N-warp: x block of 40

    int2* desc = (int2*)(smem + DESC_OFF);

    // ---- prologue: per-K-row gather descriptors (CTA-uniform) ----
    for (int k = tid; k < 576; k += THREADS) {
        int c  = k / 9;
        int t9 = k - c * 9;
        int ky = t9 / 3;
        int kx = t9 - ky * 3;
        int m5 = c % 5;
        int dy = (m5 == 2) ? 1 : ((m5 == 4) ? -1 : 0);
        int dx = (m5 == 1) ? 1 : ((m5 == 3) ? -1 : 0);
        int gy  = y - 1 + ky - dy;
        int off = kx - 1 - dx;                           // in [-2, 2]
        int rowBase = (c * (HH * WW) + gy * WW + off) * 4;  // bytes
        int flags = (((unsigned)gy < (unsigned)HH) ? 256 : 0) | (off + 2);
        desc[k] = make_int2(rowBase, flags);
    }
    __syncthreads();

    const char* xbp = (const char*)(x + (size_t)b * CIN * HH * WW);

    float acc[2][5][4];
    #pragma unroll
    for (int mf = 0; mf < 2; ++mf)
        #pragma unroll
        for (int fn = 0; fn < 5; ++fn)
            #pragma unroll
            for (int i = 0; i < 4; ++i) acc[mf][fn][i] = 0.f;

    // hoisted A-staging geometry: thread handles slots s = tid + i*256
    const int laneS = tid & 31;
    const int gS = laneS >> 2, tS = laneS & 3;
    const int qBase = tid >> 5;                  // q = qBase + i*8

    for (int ch = 0; ch < NCHUNK; ++ch) {
        char* bufA = smem + BUF_OFF + (ch & 1) * BUF_STRIDE;
        char* bufB = bufA + A_BYTES;
        const int kBase = ch * KCH;
        const int2* dch = desc + kBase;

        // ---- stage A (weights): 768 slots x 16B, 3 per thread ----
        #pragma unroll
        for (int i = 0; i < 3; ++i) {
            int q  = qBase + i * 8;              // (mf4, ks): q < 24
            int mf = q / 6;
            int ks = q - mf * 6;
            int m0 = mf * 16 + gS;
            int k0 = kBase + ks * 8 + tS;
            const float* w0 = w + m0 * 576 + k0;
            const float* w1 = w0 + 8 * 576;
            uint4 v = make_uint4(f2tf(w0[0]), f2tf(w1[0]), f2tf(w0[4]), f2tf(w1[4]));
            *(uint4*)(bufA + (tid + i * THREADS) * 16) = v;
        }

        // ---- stage B (shifted input gather): 120 pairs, 15 per warp ----
        #pragma unroll
        for (int i = 0; i < 15; ++i) {
            int p   = wid + i * 8;               // fnG*6 + ks, p < 120
            int fnG = p / 6;
            int x0  = fnG * 8 + g;               // pixel
            int kl  = (p - fnG * 6) * 8 + t;     // k within chunk
            int2 d0 = dch[kl];
            int2 d1 = dch[kl + 4];
            int gx0 = x0 + (d0.y & 255) - 2;
            int gx1 = x0 + (d1.y & 255) - 2;
            bool p0 = (d0.y & 256) && (unsigned)gx0 < (unsigned)WW;
            bool p1 = (d1.y & 256) && (unsigned)gx1 < (unsigned)WW;
            float v0 = p0 ? *(const float*)(xbp + d0.x + x0 * 4) : 0.f;
            float v1 = p1 ? *(const float*)(xbp + d1.x + x0 * 4) : 0.f;
            *(uint2*)(bufB + p * 256 + lane * 8) = make_uint2(f2tf(v0), f2tf(v1));
        }

        __syncthreads();

        // ---- compute: 6 k-steps x (2 m-frags x 5 n-frags) ----
        #pragma unroll
        for (int ks = 0; ks < 6; ++ks) {
            uint4 a0 = *(const uint4*)(bufA + (((fm * 2 + 0) * 6 + ks) * 32 + lane) * 16);
            uint4 a1 = *(const uint4*)(bufA + (((fm * 2 + 1) * 6 + ks) * 32 + lane) * 16);
            #pragma unroll
            for (int fn = 0; fn < 5; ++fn) {
                uint2 bb = *(const uint2*)(bufB +
                              (((wn * 5 + fn) * 6 + ks) * 32 + lane) * 8);
                mma_tf32(acc[0][fn], a0, bb);
                mma_tf32(acc[1][fn], a1, bb);
            }
        }
        // sync at top of next iteration's staging is implied by the one above:
        // all warps passed compute(ch-1) before staging(ch+1) overwrites, since
        // buffers alternate and one __syncthreads separates stage/compute.
    }

    // ---- epilogue ----
    #pragma unroll
    for (int mf = 0; mf < 2; ++mf) {
        int m0 = fm * 32 + mf * 16 + g;
        #pragma unroll
        for (int fn = 0; fn < 5; ++fn) {
            int xg = wn * 40 + fn * 8 + t * 2;
            float* o0 = out + (((size_t)b * COUT + m0) * HH + y) * WW + xg;
            float* o1 = o0 + 8 * HH * WW;
            *(float2*)o0 = make_float2(acc[mf][fn][0], acc[mf][fn][1]);
            *(float2*)o1 = make_float2(acc[mf][fn][2], acc[mf][fn][3]);
        }
    }
}

extern "C" void kernel_launch(void* const* d_in, const int* in_sizes, int n_in,
                              void* d_out, int out_size)
{
    const float* x = (const float*)d_in[0];
    const float* w = (const float*)d_in[1];
    float* out = (float*)d_out;

    cudaFuncSetAttribute(dconv_mma_kernel,
                         cudaFuncAttributeMaxDynamicSharedMemorySize, SMEM_TOTAL);

    dim3 grid(HH, 16);
    dconv_mma_kernel<<<grid, THREADS, SMEM_TOTAL>>>(x, w, out);
}